// round 16
// baseline (speedup 1.0000x reference)
#include <cuda_runtime.h>
#include <cuda_fp16.h>
#include <math.h>
#include <cstdint>

// ---------------------------------------------------------------------------
// AttentionHead B=4, S=2048, D=1024 — fp16 tiered precision v10 (R10 numerics).
// Fix from R15 profile: converts were throttled by the 48KB-smem GEMM kernel
// they were bundled into (2.2TB/s, occ 30%). Now: prep_all (no dynamic smem,
// transpose+split + all converts at full occupancy) -> mprime (GEMM only)
// -> dualproj -> scores -> pv (all identical to the 314.9us R10 build).
// ---------------------------------------------------------------------------

#define B_ 4
#define S_ 2048
#define D_ 1024
#define MS_ (B_ * S_)   // 8192
typedef __half hf;

// ---- scratch ----
__device__ __align__(16) hf g_qs [(size_t)MS_ * D_];
__device__ __align__(16) hf g_ks [(size_t)MS_ * D_];
__device__ __align__(16) hf g_vs [(size_t)MS_ * D_];
__device__ __align__(16) hf g_wqth[(size_t)D_ * D_];
__device__ __align__(16) hf g_wqtl[(size_t)D_ * D_];
__device__ __align__(16) hf g_wkth[(size_t)D_ * D_];
__device__ __align__(16) hf g_wktl[(size_t)D_ * D_];
__device__ __align__(16) hf g_wvs [(size_t)D_ * D_];
__device__ __align__(16) hf g_ms  [(size_t)D_ * D_];
__device__ __align__(16) hf g_qms [(size_t)MS_ * D_];
__device__ __align__(16) hf g_vts [(size_t)D_ * MS_];
__device__ __align__(16) hf g_e   [(size_t)B_ * S_ * S_];
__device__ __align__(16) float g_part [(size_t)MS_ * 32];

// ---- helpers ----
__device__ __forceinline__ uint32_t smem_u32(const void* p) {
    uint32_t a;
    asm("{ .reg .u64 t; cvta.to.shared.u64 t, %1; cvt.u32.u64 %0, t; }" : "=r"(a) : "l"(p));
    return a;
}
__device__ __forceinline__ void cp16s(uint32_t dst, const void* src) {
    asm volatile("cp.async.cg.shared.global [%0], [%1], 16;\n" :: "r"(dst), "l"(src));
}
__device__ __forceinline__ void cp_commit() { asm volatile("cp.async.commit_group;\n"); }
template <int N> __device__ __forceinline__ void cp_wait() {
    asm volatile("cp.async.wait_group %0;\n" :: "n"(N));
}
__device__ __forceinline__ void ldsm4(uint32_t (&r)[4], uint32_t addr) {
    asm volatile("ldmatrix.sync.aligned.m8n8.x4.shared.b16 {%0,%1,%2,%3}, [%4];"
                 : "=r"(r[0]), "=r"(r[1]), "=r"(r[2]), "=r"(r[3]) : "r"(addr));
}
__device__ __forceinline__ void mma_fp16(float (&d)[4], const uint32_t (&a)[4],
                                         uint32_t b0, uint32_t b1) {
    asm volatile(
        "mma.sync.aligned.m16n8k16.row.col.f32.f16.f16.f32 "
        "{%0,%1,%2,%3}, {%4,%5,%6,%7}, {%8,%9}, {%0,%1,%2,%3};\n"
        : "+f"(d[0]), "+f"(d[1]), "+f"(d[2]), "+f"(d[3])
        : "r"(a[0]), "r"(a[1]), "r"(a[2]), "r"(a[3]), "r"(b0), "r"(b1));
}
__device__ __forceinline__ void split2(float x, hf& h, hf& l) {
    h = __float2half_rn(x);
    l = __float2half_rn(x - __half2float(h));
}
__device__ __forceinline__ uint32_t packh(hf a, hf b) {
    __half2 p = __halves2half2(a, b);
    return *(uint32_t*)&p;
}

// ---------------------------------------------------------------------------
constexpr int SUB16 = 128 * 128;           // 16 KB
constexpr int STG_SS = 2 * SUB16;          // 32 KB per stage
constexpr int GSMEM_SS = 3 * STG_SS;       // 96 KB
constexpr int GSMEM_PV = GSMEM_SS + 512;

// 128-thread tile fill (8 chunks per thread)
__device__ __forceinline__ void fill_single(uint32_t dst, const hf* __restrict__ X,
                                            size_t ld, int rowbase, int k0, int tid) {
#pragma unroll
    for (int p = 0; p < 8; p++) {
        int idx = tid + p * 128;
        int r = idx >> 3, c = idx & 7;
        uint32_t off = (uint32_t)(r * 128) + ((((uint32_t)c) ^ ((uint32_t)r & 7)) << 4);
        cp16s(dst + off, X + (size_t)(rowbase + r) * ld + k0 + c * 8);
    }
}

// ---------------------------------------------------------------------------
// single x single 1-MMA body, BK=64, 4 warps, 64x64 warp tile (R10).
// EPI 2: e=rn(exp(acc/32)) -> Ch + row partials. EPI 3: fp32 * invrs[row].
// EPI 4: single fp16 out.
// ---------------------------------------------------------------------------
template <int EPI>
__device__ __forceinline__ void gemm128_ss_body(
    char* smem, const hf* __restrict__ A, const hf* __restrict__ Bx,
    size_t lda, size_t ldb, int K,
    hf* __restrict__ Ch, float* __restrict__ Cf, size_t ldc,
    float* __restrict__ part, const float* __restrict__ invrs,
    int bm, int bn, int bx)
{
    const uint32_t sbase = smem_u32(smem);
    const int tid = threadIdx.x;
    const int wid = tid >> 5, lane = tid & 31;
    const int wm = wid >> 1, wn = wid & 1;       // 2x2 warps, warp tile 64x64
    const int grp = lane >> 3, wi = lane & 7;
    const uint32_t xw = (uint32_t)wi << 4;
    const uint32_t aRow = (uint32_t)(wm * 64 + (grp & 1) * 8 + wi) * 128;
    const uint32_t bRow = (uint32_t)(wn * 64 + (grp >> 1) * 8 + wi) * 128;

    float acc[4][8][4];
#pragma unroll
    for (int i = 0; i < 4; i++)
#pragma unroll
        for (int j = 0; j < 8; j++)
#pragma unroll
            for (int r = 0; r < 4; r++) acc[i][j][r] = 0.f;

    auto fill_stage = [&](int s, int kt) {
        const uint32_t st = sbase + (uint32_t)s * STG_SS;
        const int k0 = kt * 64;
        fill_single(st,         A,  lda, bm, k0, tid);
        fill_single(st + SUB16, Bx, ldb, bn, k0, tid);
        cp_commit();
    };

    const int NT = K / 64;
    fill_stage(0, 0);
    fill_stage(1, 1);

    for (int kt = 0; kt < NT; kt++) {
        if (kt + 1 < NT) cp_wait<1>(); else cp_wait<0>();
        __syncthreads();
        if (kt + 2 < NT) fill_stage((kt + 2) % 3, kt + 2);

        const uint32_t st = sbase + (uint32_t)(kt % 3) * STG_SS;
#pragma unroll
        for (int kk = 0; kk < 4; kk++) {
            uint32_t aa[4][4];
            const uint32_t ak = ((uint32_t)(kk * 2 + (grp >> 1)) << 4) ^ xw;
#pragma unroll
            for (int mt = 0; mt < 4; mt++)
                ldsm4(aa[mt], st + aRow + (uint32_t)mt * 2048 + ak);
            const uint32_t bk = ((uint32_t)(kk * 2 + (grp & 1)) << 4) ^ xw;
#pragma unroll
            for (int np = 0; np < 4; np++) {
                uint32_t bb[4];
                ldsm4(bb, st + SUB16 + bRow + (uint32_t)np * 2048 + bk);
#pragma unroll
                for (int mt = 0; mt < 4; mt++)
#pragma unroll
                    for (int half = 0; half < 2; half++)
                        mma_fp16(acc[mt][np * 2 + half], aa[mt],
                                 bb[half * 2], bb[half * 2 + 1]);
            }
        }
    }

    const int g = lane >> 2, t = lane & 3;
#pragma unroll
    for (int mt = 0; mt < 4; mt++) {
        float p0 = 0.f, p1 = 0.f;
#pragma unroll
        for (int nt = 0; nt < 8; nt++) {
            const size_t row0 = (size_t)(bm + wm * 64 + mt * 16 + g);
            const size_t col  = (size_t)(bn + wn * 64 + nt * 8 + 2 * t);
            if (EPI == 2) {
                hf e0 = __float2half_rn(__expf(acc[mt][nt][0] * (1.f / 32.f)));
                hf e1 = __float2half_rn(__expf(acc[mt][nt][1] * (1.f / 32.f)));
                hf e2 = __float2half_rn(__expf(acc[mt][nt][2] * (1.f / 32.f)));
                hf e3 = __float2half_rn(__expf(acc[mt][nt][3] * (1.f / 32.f)));
                p0 += __half2float(e0) + __half2float(e1);
                p1 += __half2float(e2) + __half2float(e3);
                *(uint32_t*)(Ch + row0 * ldc + col)       = packh(e0, e1);
                *(uint32_t*)(Ch + (row0 + 8) * ldc + col) = packh(e2, e3);
            } else if (EPI == 3) {
                const float i0 = invrs[row0], i1 = invrs[row0 + 8];
                *(float2*)(Cf + row0 * ldc + col) =
                    make_float2(acc[mt][nt][0] * i0, acc[mt][nt][1] * i0);
                *(float2*)(Cf + (row0 + 8) * ldc + col) =
                    make_float2(acc[mt][nt][2] * i1, acc[mt][nt][3] * i1);
            } else { // EPI == 4
                *(uint32_t*)(Ch + row0 * ldc + col) =
                    packh(__float2half_rn(acc[mt][nt][0]), __float2half_rn(acc[mt][nt][1]));
                *(uint32_t*)(Ch + (row0 + 8) * ldc + col) =
                    packh(__float2half_rn(acc[mt][nt][2]), __float2half_rn(acc[mt][nt][3]));
            }
        }
        if (EPI == 2) {
            p0 += __shfl_xor_sync(0xffffffffu, p0, 1);
            p0 += __shfl_xor_sync(0xffffffffu, p0, 2);
            p1 += __shfl_xor_sync(0xffffffffu, p1, 1);
            p1 += __shfl_xor_sync(0xffffffffu, p1, 2);
            if (t == 0) {
                const int row0 = bm + wm * 64 + mt * 16 + g;
                part[(size_t)row0 * 32 + bx * 2 + wn]       = p0;
                part[(size_t)(row0 + 8) * 32 + bx * 2 + wn] = p1;
            }
        }
    }
}

// ---------------------------------------------------------------------------
// 64x64 both-split 3-MMA (M'), 256 threads.
// ---------------------------------------------------------------------------
constexpr int SUB64 = 64 * 128;
constexpr int STAGE64 = 2 * SUB64;
constexpr int GSMEM64 = 3 * STAGE64;   // 48 KB

__device__ __forceinline__ void fill64(uint32_t dst, const hf* __restrict__ H,
                                       const hf* __restrict__ L,
                                       size_t ld, int rowbase, int k0, int tid) {
#pragma unroll
    for (int p = 0; p < 2; p++) {
        int idx = tid + p * 256;
        int r = idx >> 3, c = idx & 7;
        uint32_t off = (uint32_t)(r * 128) + ((((uint32_t)c) ^ ((uint32_t)r & 7)) << 4);
        const hf* src = (c < 4)
            ? H + (size_t)(rowbase + r) * ld + k0 + c * 8
            : L + (size_t)(rowbase + r) * ld + k0 + (c - 4) * 8;
        cp16s(dst + off, src);
    }
}

__device__ __forceinline__ void gemm64_body(
    char* smem,
    const hf* __restrict__ Ah, const hf* __restrict__ Al,
    const hf* __restrict__ Bh, const hf* __restrict__ Bl,
    hf* __restrict__ Cs, int K, size_t ld, int bm, int bn)
{
    const uint32_t sbase = smem_u32(smem);
    const int tid = threadIdx.x;
    const int wid = tid >> 5, lane = tid & 31;
    const int wm = wid >> 1, wn = wid & 1;
    const int grp = lane >> 3, wi = lane & 7;
    const uint32_t xw = (uint32_t)wi << 4;
    const uint32_t aRow = (uint32_t)(wm * 16 + (grp & 1) * 8 + wi) * 128;
    const uint32_t bRow = (uint32_t)(wn * 32 + (grp >> 1) * 8 + wi) * 128;

    float acc[4][4];
#pragma unroll
    for (int j = 0; j < 4; j++)
#pragma unroll
        for (int r = 0; r < 4; r++) acc[j][r] = 0.f;

    auto fill_stage = [&](int s, int kt) {
        const uint32_t st = sbase + (uint32_t)s * STAGE64;
        fill64(st,         Ah, Al, ld, bm, kt * 32, tid);
        fill64(st + SUB64, Bh, Bl, ld, bn, kt * 32, tid);
        cp_commit();
    };

    const int NT = K / 32;
    fill_stage(0, 0);
    fill_stage(1, 1);

    for (int kt = 0; kt < NT; kt++) {
        if (kt + 1 < NT) cp_wait<1>(); else cp_wait<0>();
        __syncthreads();
        if (kt + 2 < NT) fill_stage((kt + 2) % 3, kt + 2);

        const uint32_t st = sbase + (uint32_t)(kt % 3) * STAGE64;
#pragma unroll
        for (int kk = 0; kk < 2; kk++) {
            uint32_t ah[4], al[4];
            const uint32_t ak = ((uint32_t)(kk * 2 + (grp >> 1)) << 4) ^ xw;
            const uint32_t ao = st + aRow + ak;
            ldsm4(ah, ao);
            ldsm4(al, ao ^ 64u);
            const uint32_t bk = ((uint32_t)(kk * 2 + (grp & 1)) << 4) ^ xw;
#pragma unroll
            for (int np = 0; np < 2; np++) {
                uint32_t bh[4], bl[4];
                const uint32_t bo = st + SUB64 + bRow + (uint32_t)np * 2048 + bk;
                ldsm4(bh, bo);
                ldsm4(bl, bo ^ 64u);
#pragma unroll
                for (int half = 0; half < 2; half++) {
                    const int nt = np * 2 + half;
                    const int h = half * 2;
                    mma_fp16(acc[nt], ah, bh[h], bh[h + 1]);
                    mma_fp16(acc[nt], ah, bl[h], bl[h + 1]);
                    mma_fp16(acc[nt], al, bh[h], bh[h + 1]);
                }
            }
        }
    }

    const int g = lane >> 2, t = lane & 3;
#pragma unroll
    for (int nt = 0; nt < 4; nt++) {
        const size_t row0 = (size_t)(bm + wm * 16 + g);
        const size_t col  = (size_t)(bn + wn * 32 + nt * 8 + 2 * t);
        *(uint32_t*)(Cs + row0 * ld + col) =
            packh(__float2half_rn(acc[nt][0]), __float2half_rn(acc[nt][1]));
        *(uint32_t*)(Cs + (row0 + 8) * ld + col) =
            packh(__float2half_rn(acc[nt][2]), __float2half_rn(acc[nt][3]));
    }
}

// ---------------------------------------------------------------------------
// prep_all: NO dynamic smem. blocks [0,2048): transpose+split wq/wk;
// [2048,...): q/k/v/wv single converts at full occupancy.
// ---------------------------------------------------------------------------
__device__ __forceinline__ void single_conv_block(const float* __restrict__ x,
                                                  hf* __restrict__ h, size_t bi) {
    const float4* x4 = (const float4*)x;
    uint2* h2 = (uint2*)h;
    const size_t base = bi * 2048 + threadIdx.x;
#pragma unroll
    for (int j = 0; j < 8; j++) {
        float4 vv = x4[base + j * 256];
        h2[base + j * 256] = make_uint2(
            packh(__float2half_rn(vv.x), __float2half_rn(vv.y)),
            packh(__float2half_rn(vv.z), __float2half_rn(vv.w)));
    }
}

__global__ __launch_bounds__(256)
void prep_all_kernel(const float* __restrict__ wq, hf* __restrict__ wqth, hf* __restrict__ wqtl,
                     const float* __restrict__ wk, hf* __restrict__ wkth, hf* __restrict__ wktl,
                     const float* __restrict__ q, hf* __restrict__ qs,
                     const float* __restrict__ k, hf* __restrict__ ks,
                     const float* __restrict__ v, hf* __restrict__ vs,
                     const float* __restrict__ wv, hf* __restrict__ wvs)
{
    __shared__ float tile[32][33];
    const int bx = blockIdx.x;
    if (bx < 2048) {
        const int tb = bx & 1023;
        const float* x = (bx < 1024) ? wq : wk;
        hf* h = (bx < 1024) ? wqth : wkth;
        hf* l = (bx < 1024) ? wqtl : wktl;
        const int tx = threadIdx.x & 31, ty = threadIdx.x >> 5;
        const int r0 = (tb >> 5) * 32, c0 = (tb & 31) * 32;
#pragma unroll
        for (int i = 0; i < 4; i++)
            tile[ty + i * 8][tx] = x[(size_t)(r0 + ty + i * 8) * D_ + c0 + tx];
        __syncthreads();
#pragma unroll
        for (int i = 0; i < 4; i++) {
            float vv = tile[tx][ty + i * 8];
            hf hh, ll;
            split2(vv, hh, ll);
            h[(size_t)(c0 + ty + i * 8) * D_ + r0 + tx] = hh;
            l[(size_t)(c0 + ty + i * 8) * D_ + r0 + tx] = ll;
        }
    } else {
        int b = bx - 2048;
        if (b < 1024)       single_conv_block(q, qs, (size_t)b);
        else if (b < 2048)  single_conv_block(k, ks, (size_t)(b - 1024));
        else if (b < 3072)  single_conv_block(v, vs, (size_t)(b - 2048));
        else                single_conv_block(wv, wvs, (size_t)(b - 3072));
    }
}

// mprime: M' = Wk^T Wq (3-MMA from splits), 256 blocks, 48 KB smem.
__global__ __launch_bounds__(256, 2)
void mprime_kernel(const hf* __restrict__ wkth, const hf* __restrict__ wktl,
                   const hf* __restrict__ wqth, const hf* __restrict__ wqtl,
                   hf* __restrict__ ms)
{
    extern __shared__ char smem[];
    const int bx = blockIdx.x;
    gemm64_body(smem, wkth, wktl, wqth, wqtl, ms,
                D_, D_, (bx >> 4) * 64, (bx & 15) * 64);
}

// dualproj: qM (512 blocks) + vp^T (512 blocks), single 1-MMA, 128 threads
__global__ __launch_bounds__(128, 2)
void dualproj_kernel(const hf* qs, const hf* ms, hf* qms,
                     const hf* wvs, const hf* vs, hf* vts)
{
    extern __shared__ char smem[];
    int bx = blockIdx.x;
    if (bx < 512) {
        gemm128_ss_body<4>(smem, qs, ms, D_, D_, D_, qms, nullptr, D_,
                           nullptr, nullptr, (bx >> 3) * 128, (bx & 7) * 128, 0);
    } else {
        bx -= 512;
        gemm128_ss_body<4>(smem, wvs, vs, D_, D_, D_, vts, nullptr, MS_,
                           nullptr, nullptr, (bx >> 6) * 128, (bx & 63) * 128, 0);
    }
}

// scores: e = rn(exp(qM k^T / 32)) + row partials
__global__ __launch_bounds__(128, 2)
void scores_kernel(const hf* __restrict__ qms, const hf* __restrict__ ks,
                   hf* __restrict__ e, float* __restrict__ part)
{
    extern __shared__ char smem[];
    const size_t zq = (size_t)blockIdx.z * S_ * D_;
    gemm128_ss_body<2>(smem, qms + zq, ks + zq, D_, D_, D_,
                       e + (size_t)blockIdx.z * S_ * S_, nullptr, S_,
                       part + (size_t)blockIdx.z * S_ * 32, nullptr,
                       blockIdx.y * 128, blockIdx.x * 128, blockIdx.x);
}

// pv: invrs for its 128 rows in smem, then out = diag(invrs) e vp
__global__ __launch_bounds__(128, 2)
void pv_kernel(const hf* __restrict__ e, const hf* __restrict__ vts,
               float* __restrict__ out, const float* __restrict__ part)
{
    extern __shared__ char smem[];
    float* sInv = (float*)(smem + GSMEM_SS);
    const int bm = blockIdx.y * 128;
    const float* pz = part + (size_t)blockIdx.z * S_ * 32;
    {
        const float* pr = pz + (size_t)(bm + threadIdx.x) * 32;
        float s = 0.f;
#pragma unroll
        for (int j = 0; j < 32; j++) s += pr[j];
        sInv[threadIdx.x] = 1.f / s;
    }
    __syncthreads();

    gemm128_ss_body<3>(smem, e + (size_t)blockIdx.z * S_ * S_,
                       vts + (size_t)blockIdx.z * S_, S_, MS_, S_,
                       nullptr, out + (size_t)blockIdx.z * S_ * D_, D_,
                       nullptr, sInv - bm,
                       bm, blockIdx.x * 128, 0);
}

// ---------------------------------------------------------------------------
extern "C" void kernel_launch(void* const* d_in, const int* in_sizes, int n_in,
                              void* d_out, int out_size)
{
    const float* q  = (const float*)d_in[0];
    const float* k  = (const float*)d_in[1];
    const float* v  = (const float*)d_in[2];
    const float* wq = (const float*)d_in[3];
    const float* wk = (const float*)d_in[4];
    const float* wv = (const float*)d_in[5];
    float* out = (float*)d_out;

    hf *qs, *ks, *vs, *wvs;
    hf *wqth, *wqtl, *wkth, *wktl;
    hf *ms, *qms, *vts, *e;
    float *part;
    cudaGetSymbolAddress((void**)&qs, g_qs);     cudaGetSymbolAddress((void**)&ks, g_ks);
    cudaGetSymbolAddress((void**)&vs, g_vs);     cudaGetSymbolAddress((void**)&wvs, g_wvs);
    cudaGetSymbolAddress((void**)&wqth, g_wqth); cudaGetSymbolAddress((void**)&wqtl, g_wqtl);
    cudaGetSymbolAddress((void**)&wkth, g_wkth); cudaGetSymbolAddress((void**)&wktl, g_wktl);
    cudaGetSymbolAddress((void**)&ms, g_ms);     cudaGetSymbolAddress((void**)&qms, g_qms);
    cudaGetSymbolAddress((void**)&vts, g_vts);   cudaGetSymbolAddress((void**)&e, g_e);
    cudaGetSymbolAddress((void**)&part, g_part);

    cudaFuncSetAttribute(mprime_kernel,   cudaFuncAttributeMaxDynamicSharedMemorySize, GSMEM64);
    cudaFuncSetAttribute(dualproj_kernel, cudaFuncAttributeMaxDynamicSharedMemorySize, GSMEM_SS);
    cudaFuncSetAttribute(scores_kernel,   cudaFuncAttributeMaxDynamicSharedMemorySize, GSMEM_SS);
    cudaFuncSetAttribute(pv_kernel,       cudaFuncAttributeMaxDynamicSharedMemorySize, GSMEM_PV);

    // 1) all bandwidth prep at full occupancy (no dynamic smem):
    //    wq/wk transpose+split (2048 blocks) + q/k/v/wv converts (3200 blocks)
    prep_all_kernel<<<2048 + 3 * 1024 + 128, 256>>>(
        wq, wqth, wqtl, wk, wkth, wktl, q, qs, k, ks, v, vs, wv, wvs);

    // 2) M' = Wk^T Wq (GEMM-only kernel keeps its 48KB smem)
    mprime_kernel<<<256, 256, GSMEM64>>>(wkth, wktl, wqth, wqtl, ms);

    // 3) qM = q M'^T and vp^T = Wv v^T (one launch)
    dualproj_kernel<<<1024, 128, GSMEM_SS>>>(qs, ms, qms, wvs, vs, vts);

    // 4) e = exp(qM k^T / 32) + row partials
    dim3 gs(16, 16, B_);
    scores_kernel<<<gs, 128, GSMEM_SS>>>(qms, ks, e, part);

    // 5) out = diag(1/rowsum) e vp  (invrs computed in-kernel)
    dim3 go(8, 16, B_);
    pv_kernel<<<go, 128, GSMEM_PV>>>(e, vts, out, part);
}

// round 17
// speedup vs baseline: 1.0326x; 1.0326x over previous
#include <cuda_runtime.h>
#include <cuda_fp16.h>
#include <math.h>
#include <cstdint>

// ---------------------------------------------------------------------------
// AttentionHead B=4, S=2048, D=1024 — fp16 tiered precision (R10 build, exact).
// M' = Wk^T Wq (3-MMA from weight splits). qM = q x M' (1-MMA).
// scores = qM x k (1-MMA). vp^T = Wv x v (1-MMA). PV = e x vp (1-MMA).
// Softmax fused: scores epilogue exp+partials; pv computes 1/rowsum in smem.
// ---------------------------------------------------------------------------

#define B_ 4
#define S_ 2048
#define D_ 1024
#define MS_ (B_ * S_)   // 8192
typedef __half hf;

// ---- scratch ----
__device__ __align__(16) hf g_qs [(size_t)MS_ * D_];
__device__ __align__(16) hf g_ks [(size_t)MS_ * D_];
__device__ __align__(16) hf g_vs [(size_t)MS_ * D_];
__device__ __align__(16) hf g_wqth[(size_t)D_ * D_];
__device__ __align__(16) hf g_wqtl[(size_t)D_ * D_];
__device__ __align__(16) hf g_wkth[(size_t)D_ * D_];
__device__ __align__(16) hf g_wktl[(size_t)D_ * D_];
__device__ __align__(16) hf g_wvs [(size_t)D_ * D_];
__device__ __align__(16) hf g_ms  [(size_t)D_ * D_];
__device__ __align__(16) hf g_qms [(size_t)MS_ * D_];
__device__ __align__(16) hf g_vts [(size_t)D_ * MS_];
__device__ __align__(16) hf g_e   [(size_t)B_ * S_ * S_];
__device__ __align__(16) float g_part [(size_t)MS_ * 32];

// ---- helpers ----
__device__ __forceinline__ uint32_t smem_u32(const void* p) {
    uint32_t a;
    asm("{ .reg .u64 t; cvta.to.shared.u64 t, %1; cvt.u32.u64 %0, t; }" : "=r"(a) : "l"(p));
    return a;
}
__device__ __forceinline__ void cp16s(uint32_t dst, const void* src) {
    asm volatile("cp.async.cg.shared.global [%0], [%1], 16;\n" :: "r"(dst), "l"(src));
}
__device__ __forceinline__ void cp_commit() { asm volatile("cp.async.commit_group;\n"); }
template <int N> __device__ __forceinline__ void cp_wait() {
    asm volatile("cp.async.wait_group %0;\n" :: "n"(N));
}
__device__ __forceinline__ void ldsm4(uint32_t (&r)[4], uint32_t addr) {
    asm volatile("ldmatrix.sync.aligned.m8n8.x4.shared.b16 {%0,%1,%2,%3}, [%4];"
                 : "=r"(r[0]), "=r"(r[1]), "=r"(r[2]), "=r"(r[3]) : "r"(addr));
}
__device__ __forceinline__ void mma_fp16(float (&d)[4], const uint32_t (&a)[4],
                                         uint32_t b0, uint32_t b1) {
    asm volatile(
        "mma.sync.aligned.m16n8k16.row.col.f32.f16.f16.f32 "
        "{%0,%1,%2,%3}, {%4,%5,%6,%7}, {%8,%9}, {%0,%1,%2,%3};\n"
        : "+f"(d[0]), "+f"(d[1]), "+f"(d[2]), "+f"(d[3])
        : "r"(a[0]), "r"(a[1]), "r"(a[2]), "r"(a[3]), "r"(b0), "r"(b1));
}
__device__ __forceinline__ void split2(float x, hf& h, hf& l) {
    h = __float2half_rn(x);
    l = __float2half_rn(x - __half2float(h));
}
__device__ __forceinline__ uint32_t packh(hf a, hf b) {
    __half2 p = __halves2half2(a, b);
    return *(uint32_t*)&p;
}

// ---------------------------------------------------------------------------
constexpr int SUB16 = 128 * 128;           // 16 KB
constexpr int STG_SS = 2 * SUB16;          // 32 KB per stage
constexpr int GSMEM_SS = 3 * STG_SS;       // 96 KB
constexpr int GSMEM_PV = GSMEM_SS + 512;

// 128-thread tile fill (8 chunks per thread)
__device__ __forceinline__ void fill_single(uint32_t dst, const hf* __restrict__ X,
                                            size_t ld, int rowbase, int k0, int tid) {
#pragma unroll
    for (int p = 0; p < 8; p++) {
        int idx = tid + p * 128;
        int r = idx >> 3, c = idx & 7;
        uint32_t off = (uint32_t)(r * 128) + ((((uint32_t)c) ^ ((uint32_t)r & 7)) << 4);
        cp16s(dst + off, X + (size_t)(rowbase + r) * ld + k0 + c * 8);
    }
}

// ---------------------------------------------------------------------------
// single x single 1-MMA body, BK=64, 4 warps, 64x64 warp tile.
// EPI 2: e=rn(exp(acc/32)) -> Ch + row partials. EPI 3: fp32 * invrs[row].
// EPI 4: single fp16 out.
// ---------------------------------------------------------------------------
template <int EPI>
__device__ __forceinline__ void gemm128_ss_body(
    char* smem, const hf* __restrict__ A, const hf* __restrict__ Bx,
    size_t lda, size_t ldb, int K,
    hf* __restrict__ Ch, float* __restrict__ Cf, size_t ldc,
    float* __restrict__ part, const float* __restrict__ invrs,
    int bm, int bn, int bx)
{
    const uint32_t sbase = smem_u32(smem);
    const int tid = threadIdx.x;
    const int wid = tid >> 5, lane = tid & 31;
    const int wm = wid >> 1, wn = wid & 1;       // 2x2 warps, warp tile 64x64
    const int grp = lane >> 3, wi = lane & 7;
    const uint32_t xw = (uint32_t)wi << 4;
    const uint32_t aRow = (uint32_t)(wm * 64 + (grp & 1) * 8 + wi) * 128;
    const uint32_t bRow = (uint32_t)(wn * 64 + (grp >> 1) * 8 + wi) * 128;

    float acc[4][8][4];
#pragma unroll
    for (int i = 0; i < 4; i++)
#pragma unroll
        for (int j = 0; j < 8; j++)
#pragma unroll
            for (int r = 0; r < 4; r++) acc[i][j][r] = 0.f;

    auto fill_stage = [&](int s, int kt) {
        const uint32_t st = sbase + (uint32_t)s * STG_SS;
        const int k0 = kt * 64;
        fill_single(st,         A,  lda, bm, k0, tid);
        fill_single(st + SUB16, Bx, ldb, bn, k0, tid);
        cp_commit();
    };

    const int NT = K / 64;
    fill_stage(0, 0);
    fill_stage(1, 1);

    for (int kt = 0; kt < NT; kt++) {
        if (kt + 1 < NT) cp_wait<1>(); else cp_wait<0>();
        __syncthreads();
        if (kt + 2 < NT) fill_stage((kt + 2) % 3, kt + 2);

        const uint32_t st = sbase + (uint32_t)(kt % 3) * STG_SS;
#pragma unroll
        for (int kk = 0; kk < 4; kk++) {
            uint32_t aa[4][4];
            const uint32_t ak = ((uint32_t)(kk * 2 + (grp >> 1)) << 4) ^ xw;
#pragma unroll
            for (int mt = 0; mt < 4; mt++)
                ldsm4(aa[mt], st + aRow + (uint32_t)mt * 2048 + ak);
            const uint32_t bk = ((uint32_t)(kk * 2 + (grp & 1)) << 4) ^ xw;
#pragma unroll
            for (int np = 0; np < 4; np++) {
                uint32_t bb[4];
                ldsm4(bb, st + SUB16 + bRow + (uint32_t)np * 2048 + bk);
#pragma unroll
                for (int mt = 0; mt < 4; mt++)
#pragma unroll
                    for (int half = 0; half < 2; half++)
                        mma_fp16(acc[mt][np * 2 + half], aa[mt],
                                 bb[half * 2], bb[half * 2 + 1]);
            }
        }
    }

    const int g = lane >> 2, t = lane & 3;
#pragma unroll
    for (int mt = 0; mt < 4; mt++) {
        float p0 = 0.f, p1 = 0.f;
#pragma unroll
        for (int nt = 0; nt < 8; nt++) {
            const size_t row0 = (size_t)(bm + wm * 64 + mt * 16 + g);
            const size_t col  = (size_t)(bn + wn * 64 + nt * 8 + 2 * t);
            if (EPI == 2) {
                hf e0 = __float2half_rn(__expf(acc[mt][nt][0] * (1.f / 32.f)));
                hf e1 = __float2half_rn(__expf(acc[mt][nt][1] * (1.f / 32.f)));
                hf e2 = __float2half_rn(__expf(acc[mt][nt][2] * (1.f / 32.f)));
                hf e3 = __float2half_rn(__expf(acc[mt][nt][3] * (1.f / 32.f)));
                p0 += __half2float(e0) + __half2float(e1);
                p1 += __half2float(e2) + __half2float(e3);
                *(uint32_t*)(Ch + row0 * ldc + col)       = packh(e0, e1);
                *(uint32_t*)(Ch + (row0 + 8) * ldc + col) = packh(e2, e3);
            } else if (EPI == 3) {
                const float i0 = invrs[row0], i1 = invrs[row0 + 8];
                *(float2*)(Cf + row0 * ldc + col) =
                    make_float2(acc[mt][nt][0] * i0, acc[mt][nt][1] * i0);
                *(float2*)(Cf + (row0 + 8) * ldc + col) =
                    make_float2(acc[mt][nt][2] * i1, acc[mt][nt][3] * i1);
            } else { // EPI == 4
                *(uint32_t*)(Ch + row0 * ldc + col) =
                    packh(__float2half_rn(acc[mt][nt][0]), __float2half_rn(acc[mt][nt][1]));
                *(uint32_t*)(Ch + (row0 + 8) * ldc + col) =
                    packh(__float2half_rn(acc[mt][nt][2]), __float2half_rn(acc[mt][nt][3]));
            }
        }
        if (EPI == 2) {
            p0 += __shfl_xor_sync(0xffffffffu, p0, 1);
            p0 += __shfl_xor_sync(0xffffffffu, p0, 2);
            p1 += __shfl_xor_sync(0xffffffffu, p1, 1);
            p1 += __shfl_xor_sync(0xffffffffu, p1, 2);
            if (t == 0) {
                const int row0 = bm + wm * 64 + mt * 16 + g;
                part[(size_t)row0 * 32 + bx * 2 + wn]       = p0;
                part[(size_t)(row0 + 8) * 32 + bx * 2 + wn] = p1;
            }
        }
    }
}

// ---------------------------------------------------------------------------
// 64x64 both-split 3-MMA (M'), 256 threads.
// ---------------------------------------------------------------------------
constexpr int SUB64 = 64 * 128;
constexpr int STAGE64 = 2 * SUB64;
constexpr int GSMEM64 = 3 * STAGE64;   // 48 KB

__device__ __forceinline__ void fill64(uint32_t dst, const hf* __restrict__ H,
                                       const hf* __restrict__ L,
                                       size_t ld, int rowbase, int k0, int tid) {
#pragma unroll
    for (int p = 0; p < 2; p++) {
        int idx = tid + p * 256;
        int r = idx >> 3, c = idx & 7;
        uint32_t off = (uint32_t)(r * 128) + ((((uint32_t)c) ^ ((uint32_t)r & 7)) << 4);
        const hf* src = (c < 4)
            ? H + (size_t)(rowbase + r) * ld + k0 + c * 8
            : L + (size_t)(rowbase + r) * ld + k0 + (c - 4) * 8;
        cp16s(dst + off, src);
    }
}

__device__ __forceinline__ void gemm64_body(
    char* smem,
    const hf* __restrict__ Ah, const hf* __restrict__ Al,
    const hf* __restrict__ Bh, const hf* __restrict__ Bl,
    hf* __restrict__ Cs, int K, size_t ld, int bm, int bn)
{
    const uint32_t sbase = smem_u32(smem);
    const int tid = threadIdx.x;
    const int wid = tid >> 5, lane = tid & 31;
    const int wm = wid >> 1, wn = wid & 1;
    const int grp = lane >> 3, wi = lane & 7;
    const uint32_t xw = (uint32_t)wi << 4;
    const uint32_t aRow = (uint32_t)(wm * 16 + (grp & 1) * 8 + wi) * 128;
    const uint32_t bRow = (uint32_t)(wn * 32 + (grp >> 1) * 8 + wi) * 128;

    float acc[4][4];
#pragma unroll
    for (int j = 0; j < 4; j++)
#pragma unroll
        for (int r = 0; r < 4; r++) acc[j][r] = 0.f;

    auto fill_stage = [&](int s, int kt) {
        const uint32_t st = sbase + (uint32_t)s * STAGE64;
        fill64(st,         Ah, Al, ld, bm, kt * 32, tid);
        fill64(st + SUB64, Bh, Bl, ld, bn, kt * 32, tid);
        cp_commit();
    };

    const int NT = K / 32;
    fill_stage(0, 0);
    fill_stage(1, 1);

    for (int kt = 0; kt < NT; kt++) {
        if (kt + 1 < NT) cp_wait<1>(); else cp_wait<0>();
        __syncthreads();
        if (kt + 2 < NT) fill_stage((kt + 2) % 3, kt + 2);

        const uint32_t st = sbase + (uint32_t)(kt % 3) * STAGE64;
#pragma unroll
        for (int kk = 0; kk < 2; kk++) {
            uint32_t ah[4], al[4];
            const uint32_t ak = ((uint32_t)(kk * 2 + (grp >> 1)) << 4) ^ xw;
            const uint32_t ao = st + aRow + ak;
            ldsm4(ah, ao);
            ldsm4(al, ao ^ 64u);
            const uint32_t bk = ((uint32_t)(kk * 2 + (grp & 1)) << 4) ^ xw;
#pragma unroll
            for (int np = 0; np < 2; np++) {
                uint32_t bh[4], bl[4];
                const uint32_t bo = st + SUB64 + bRow + (uint32_t)np * 2048 + bk;
                ldsm4(bh, bo);
                ldsm4(bl, bo ^ 64u);
#pragma unroll
                for (int half = 0; half < 2; half++) {
                    const int nt = np * 2 + half;
                    const int h = half * 2;
                    mma_fp16(acc[nt], ah, bh[h], bh[h + 1]);
                    mma_fp16(acc[nt], ah, bl[h], bl[h + 1]);
                    mma_fp16(acc[nt], al, bh[h], bh[h + 1]);
                }
            }
        }
    }

    const int g = lane >> 2, t = lane & 3;
#pragma unroll
    for (int nt = 0; nt < 4; nt++) {
        const size_t row0 = (size_t)(bm + wm * 16 + g);
        const size_t col  = (size_t)(bn + wn * 32 + nt * 8 + 2 * t);
        *(uint32_t*)(Cs + row0 * ld + col) =
            packh(__float2half_rn(acc[nt][0]), __float2half_rn(acc[nt][1]));
        *(uint32_t*)(Cs + (row0 + 8) * ld + col) =
            packh(__float2half_rn(acc[nt][2]), __float2half_rn(acc[nt][3]));
    }
}

// ---------------------------------------------------------------------------
// prep1: transpose+split wq, wk
// ---------------------------------------------------------------------------
__global__ __launch_bounds__(256)
void prep1_kernel(const float* __restrict__ wq, hf* __restrict__ wqth, hf* __restrict__ wqtl,
                  const float* __restrict__ wk, hf* __restrict__ wkth, hf* __restrict__ wktl)
{
    __shared__ float tile[32][33];
    const int tb = blockIdx.x & 1023;
    const float* x = (blockIdx.x < 1024) ? wq : wk;
    hf* h = (blockIdx.x < 1024) ? wqth : wkth;
    hf* l = (blockIdx.x < 1024) ? wqtl : wktl;
    const int tx = threadIdx.x & 31, ty = threadIdx.x >> 5;
    const int r0 = (tb >> 5) * 32, c0 = (tb & 31) * 32;
#pragma unroll
    for (int i = 0; i < 4; i++)
        tile[ty + i * 8][tx] = x[(size_t)(r0 + ty + i * 8) * D_ + c0 + tx];
    __syncthreads();
#pragma unroll
    for (int i = 0; i < 4; i++) {
        float vv = tile[tx][ty + i * 8];
        hf hh, ll;
        split2(vv, hh, ll);
        h[(size_t)(c0 + ty + i * 8) * D_ + r0 + tx] = hh;
        l[(size_t)(c0 + ty + i * 8) * D_ + r0 + tx] = ll;
    }
}

// ---------------------------------------------------------------------------
// prep2: [0,256) M' 64x64; then q, k, v, wv single converts.
// ---------------------------------------------------------------------------
__device__ __forceinline__ void single_conv_block(const float* __restrict__ x,
                                                  hf* __restrict__ h, size_t bi) {
    const float4* x4 = (const float4*)x;
    uint2* h2 = (uint2*)h;
    const size_t base = bi * 2048 + threadIdx.x;
#pragma unroll
    for (int j = 0; j < 8; j++) {
        float4 vv = x4[base + j * 256];
        h2[base + j * 256] = make_uint2(
            packh(__float2half_rn(vv.x), __float2half_rn(vv.y)),
            packh(__float2half_rn(vv.z), __float2half_rn(vv.w)));
    }
}

__global__ __launch_bounds__(256, 2)
void prep2_kernel(const hf* __restrict__ wkth, const hf* __restrict__ wktl,
                  const hf* __restrict__ wqth, const hf* __restrict__ wqtl,
                  hf* __restrict__ ms,
                  const float* __restrict__ q, hf* __restrict__ qs,
                  const float* __restrict__ k, hf* __restrict__ ks,
                  const float* __restrict__ v, hf* __restrict__ vs,
                  const float* __restrict__ wv, hf* __restrict__ wvs)
{
    extern __shared__ char smem[];
    const int bx = blockIdx.x;
    if (bx < 256) {
        gemm64_body(smem, wkth, wktl, wqth, wqtl, ms,
                    D_, D_, (bx >> 4) * 64, (bx & 15) * 64);
    } else {
        int b = bx - 256;
        if (b < 1024)       single_conv_block(q, qs, (size_t)b);
        else if (b < 2048)  single_conv_block(k, ks, (size_t)(b - 1024));
        else if (b < 3072)  single_conv_block(v, vs, (size_t)(b - 2048));
        else                single_conv_block(wv, wvs, (size_t)(b - 3072));
    }
}

// ---------------------------------------------------------------------------
// dualproj: qM (512 blocks) + vp^T (512 blocks), single 1-MMA, 128 threads
// ---------------------------------------------------------------------------
__global__ __launch_bounds__(128, 2)
void dualproj_kernel(const hf* qs, const hf* ms, hf* qms,
                     const hf* wvs, const hf* vs, hf* vts)
{
    extern __shared__ char smem[];
    int bx = blockIdx.x;
    if (bx < 512) {
        gemm128_ss_body<4>(smem, qs, ms, D_, D_, D_, qms, nullptr, D_,
                           nullptr, nullptr, (bx >> 3) * 128, (bx & 7) * 128, 0);
    } else {
        bx -= 512;
        gemm128_ss_body<4>(smem, wvs, vs, D_, D_, D_, vts, nullptr, MS_,
                           nullptr, nullptr, (bx >> 6) * 128, (bx & 63) * 128, 0);
    }
}

// scores: e = rn(exp(qM k^T / 32)) + row partials
__global__ __launch_bounds__(128, 2)
void scores_kernel(const hf* __restrict__ qms, const hf* __restrict__ ks,
                   hf* __restrict__ e, float* __restrict__ part)
{
    extern __shared__ char smem[];
    const size_t zq = (size_t)blockIdx.z * S_ * D_;
    gemm128_ss_body<2>(smem, qms + zq, ks + zq, D_, D_, D_,
                       e + (size_t)blockIdx.z * S_ * S_, nullptr, S_,
                       part + (size_t)blockIdx.z * S_ * 32, nullptr,
                       blockIdx.y * 128, blockIdx.x * 128, blockIdx.x);
}

// pv: computes invrs for its 128 rows into smem, then out = diag(invrs) e vp
__global__ __launch_bounds__(128, 2)
void pv_kernel(const hf* __restrict__ e, const hf* __restrict__ vts,
               float* __restrict__ out, const float* __restrict__ part)
{
    extern __shared__ char smem[];
    float* sInv = (float*)(smem + GSMEM_SS);
    const int bm = blockIdx.y * 128;
    const float* pz = part + (size_t)blockIdx.z * S_ * 32;
    {
        const float* pr = pz + (size_t)(bm + threadIdx.x) * 32;
        float s = 0.f;
#pragma unroll
        for (int j = 0; j < 32; j++) s += pr[j];
        sInv[threadIdx.x] = 1.f / s;
    }
    __syncthreads();

    gemm128_ss_body<3>(smem, e + (size_t)blockIdx.z * S_ * S_,
                       vts + (size_t)blockIdx.z * S_, S_, MS_, S_,
                       nullptr, out + (size_t)blockIdx.z * S_ * D_, D_,
                       nullptr, sInv - bm,
                       bm, blockIdx.x * 128, 0);
}

// ---------------------------------------------------------------------------
extern "C" void kernel_launch(void* const* d_in, const int* in_sizes, int n_in,
                              void* d_out, int out_size)
{
    const float* q  = (const float*)d_in[0];
    const float* k  = (const float*)d_in[1];
    const float* v  = (const float*)d_in[2];
    const float* wq = (const float*)d_in[3];
    const float* wk = (const float*)d_in[4];
    const float* wv = (const float*)d_in[5];
    float* out = (float*)d_out;

    hf *qs, *ks, *vs, *wvs;
    hf *wqth, *wqtl, *wkth, *wktl;
    hf *ms, *qms, *vts, *e;
    float *part;
    cudaGetSymbolAddress((void**)&qs, g_qs);     cudaGetSymbolAddress((void**)&ks, g_ks);
    cudaGetSymbolAddress((void**)&vs, g_vs);     cudaGetSymbolAddress((void**)&wvs, g_wvs);
    cudaGetSymbolAddress((void**)&wqth, g_wqth); cudaGetSymbolAddress((void**)&wqtl, g_wqtl);
    cudaGetSymbolAddress((void**)&wkth, g_wkth); cudaGetSymbolAddress((void**)&wktl, g_wktl);
    cudaGetSymbolAddress((void**)&ms, g_ms);     cudaGetSymbolAddress((void**)&qms, g_qms);
    cudaGetSymbolAddress((void**)&vts, g_vts);   cudaGetSymbolAddress((void**)&e, g_e);
    cudaGetSymbolAddress((void**)&part, g_part);

    cudaFuncSetAttribute(prep2_kernel,    cudaFuncAttributeMaxDynamicSharedMemorySize, GSMEM64);
    cudaFuncSetAttribute(dualproj_kernel, cudaFuncAttributeMaxDynamicSharedMemorySize, GSMEM_SS);
    cudaFuncSetAttribute(scores_kernel,   cudaFuncAttributeMaxDynamicSharedMemorySize, GSMEM_SS);
    cudaFuncSetAttribute(pv_kernel,       cudaFuncAttributeMaxDynamicSharedMemorySize, GSMEM_PV);

    // 1) transpose+split wq, wk
    prep1_kernel<<<2048, 256>>>(wq, wqth, wqtl, wk, wkth, wktl);

    // 2) M' (256 blocks) + q/k/v/wv single converts
    prep2_kernel<<<256 + 3 * 1024 + 128, 256, GSMEM64>>>(
        wkth, wktl, wqth, wqtl, ms,
        q, qs, k, ks, v, vs, wv, wvs);

    // 3) qM = q M'^T and vp^T = Wv v^T (one launch)
    dualproj_kernel<<<1024, 128, GSMEM_SS>>>(qs, ms, qms, wvs, vs, vts);

    // 4) e = exp(qM k^T / 32) + row partials
    dim3 gs(16, 16, B_);
    scores_kernel<<<gs, 128, GSMEM_SS>>>(qms, ks, e, part);

    // 5) out = diag(1/rowsum) e vp  (invrs computed in-kernel)
    dim3 go(8, 16, B_);
    pv_kernel<<<go, 128, GSMEM_PV>>>(e, vts, out, part);
}